// round 7
// baseline (speedup 1.0000x reference)
#include <cuda_runtime.h>
#include <math.h>

// ---------------------------------------------------------------------------
#define FMP     40
#define HW      1600
#define BPC     5
#define NBOX    8000
#define NCLS    80
#define KDIM    512
#define MCOLS   432
#define CONF_TH 0.3f
#define NMS_TH  0.5f

#define OUT_SCORE  32000
#define OUT_LABEL  40000
#define OUT_KEEP   48000

__constant__ float c_anchor_w[5] = {17.f, 55.f, 92.f, 202.f, 289.f};
__constant__ float c_anchor_h[5] = {25.f, 75.f, 206.f, 21.f, 311.f};

__device__ float g_outmat[HW * MCOLS];   // [cell][col]: 0..399 cls, 400..404 obj, 405..424 reg, pad
__device__ float g_b2[NBOX * 4];
__device__ float g_score[NBOX];
__device__ int   g_cls_count[NCLS];
__device__ int   g_cls_list[NCLS * NBOX];

typedef unsigned long long ull;

__device__ __forceinline__ void ffma2(ull& d, ull a, ull b) {
    asm("fma.rn.f32x2 %0, %1, %2, %0;" : "+l"(d) : "l"(a), "l"(b));
}
__device__ __forceinline__ float2 unpk(ull v) {
    float2 f; asm("mov.b64 {%0, %1}, %2;" : "=f"(f.x), "=f"(f.y) : "l"(v)); return f;
}
__device__ __forceinline__ float sigmoidf_(float x) { return 1.f / (1.f + expf(-x)); }

// ---------------------------------------------------------------------------
// GEMM (f32x2): tile M64 x N64, BK=16, 128 threads, thread tile 4m x 8n.
// A stored into smem PRE-DUPLICATED as (w,w) pairs (no dup MOVs in mainloop).
// Per thread-k: 4 LDS.128 + 16 FFMA2 -> fma-pipe bound.
// Grid (25 n-tiles, 8 m-tiles) = 200 blocks. Strict column ownership:
// m-tiles 0..6 write only cols < 400; m-tile 7 alone owns cols 400..431.
__global__ __launch_bounds__(128) void gemm_kernel(
    const float* __restrict__ cls_feat, const float* __restrict__ reg_feat,
    const float* __restrict__ w_obj, const float* __restrict__ b_obj,
    const float* __restrict__ w_cls, const float* __restrict__ b_cls,
    const float* __restrict__ w_reg, const float* __restrict__ b_reg)
{
    __shared__ __align__(16) float sA[2][16][128];   // [buf][k][2*m] dup pairs
    __shared__ __align__(16) float sB[2][16][64];    // [buf][k][n]

    const int bx = blockIdx.x;          // n-tile (0..24)
    const int by = blockIdx.y;          // m-tile (0..7)
    const int tid = threadIdx.x;        // 0..127
    const int tx = tid & 7;             // n-group: 8n each
    const int ty = tid >> 3;            // m-group: 4m each (0..15)
    const int n0 = bx * 64;

    if (bx == 0 && by == 0 && tid < NCLS) g_cls_count[tid] = 0;

    const float* F = (by < 7) ? cls_feat : reg_feat;

    // --- A-load: 64 rows x 16 k = 256 float4; 2 per thread ---
    const int arow0 = tid >> 2;          // 0..31
    const int arow1 = 32 + (tid >> 2);   // 32..63
    const int akc   = (tid & 3) * 4;     // k offset 0/4/8/12
    const float* ap0 = 0;
    const float* ap1 = 0;
    if (by < 7) {
        int g0 = by * 64 + arow0; if (g0 < 400) ap0 = w_cls + g0 * KDIM;
        int g1 = by * 64 + arow1; if (g1 < 400) ap1 = w_cls + g1 * KDIM;
    } else {
        if (arow0 < 5)       ap0 = w_obj + arow0 * KDIM;
        else if (arow0 < 25) ap0 = w_reg + (arow0 - 5) * KDIM;
        // arow1 >= 32 -> always null for tile 7
    }

    // --- B-load: 16 k x 64 n = 256 float4; 2 per thread ---
    const int bk0 = tid >> 4;            // 0..7 (second is +8)
    const int bn  = (tid & 15) * 4;

    float4 ra0, ra1, rb0, rb1;

    ull acc[4][4];
#pragma unroll
    for (int i = 0; i < 4; i++)
#pragma unroll
        for (int j = 0; j < 4; j++) acc[i][j] = 0ULL;

    // prologue load (k0 = 0)
    {
        const int k0 = 0;
        ra0 = ap0 ? *(const float4*)(ap0 + k0 + akc) : make_float4(0.f, 0.f, 0.f, 0.f);
        ra1 = ap1 ? *(const float4*)(ap1 + k0 + akc) : make_float4(0.f, 0.f, 0.f, 0.f);
        rb0 = *(const float4*)(F + (k0 + bk0) * HW + n0 + bn);
        rb1 = *(const float4*)(F + (k0 + bk0 + 8) * HW + n0 + bn);
        *(float2*)&sA[0][akc + 0][arow0 * 2] = make_float2(ra0.x, ra0.x);
        *(float2*)&sA[0][akc + 1][arow0 * 2] = make_float2(ra0.y, ra0.y);
        *(float2*)&sA[0][akc + 2][arow0 * 2] = make_float2(ra0.z, ra0.z);
        *(float2*)&sA[0][akc + 3][arow0 * 2] = make_float2(ra0.w, ra0.w);
        *(float2*)&sA[0][akc + 0][arow1 * 2] = make_float2(ra1.x, ra1.x);
        *(float2*)&sA[0][akc + 1][arow1 * 2] = make_float2(ra1.y, ra1.y);
        *(float2*)&sA[0][akc + 2][arow1 * 2] = make_float2(ra1.z, ra1.z);
        *(float2*)&sA[0][akc + 3][arow1 * 2] = make_float2(ra1.w, ra1.w);
        *(float4*)&sB[0][bk0][bn]     = rb0;
        *(float4*)&sB[0][bk0 + 8][bn] = rb1;
    }
    __syncthreads();

    int p = 0;
    for (int kb = 1; kb <= 32; kb++) {
        if (kb < 32) {
            const int k0 = kb * 16;
            ra0 = ap0 ? *(const float4*)(ap0 + k0 + akc) : make_float4(0.f, 0.f, 0.f, 0.f);
            ra1 = ap1 ? *(const float4*)(ap1 + k0 + akc) : make_float4(0.f, 0.f, 0.f, 0.f);
            rb0 = *(const float4*)(F + (k0 + bk0) * HW + n0 + bn);
            rb1 = *(const float4*)(F + (k0 + bk0 + 8) * HW + n0 + bn);
        }
#pragma unroll
        for (int k = 0; k < 16; k++) {
            ulonglong2 a01 = *(const ulonglong2*)&sA[p][k][ty * 8];
            ulonglong2 a23 = *(const ulonglong2*)&sA[p][k][ty * 8 + 4];
            ulonglong2 b01 = *(const ulonglong2*)&sB[p][k][tx * 8];
            ulonglong2 b23 = *(const ulonglong2*)&sB[p][k][tx * 8 + 4];
            ffma2(acc[0][0], a01.x, b01.x); ffma2(acc[0][1], a01.x, b01.y);
            ffma2(acc[0][2], a01.x, b23.x); ffma2(acc[0][3], a01.x, b23.y);
            ffma2(acc[1][0], a01.y, b01.x); ffma2(acc[1][1], a01.y, b01.y);
            ffma2(acc[1][2], a01.y, b23.x); ffma2(acc[1][3], a01.y, b23.y);
            ffma2(acc[2][0], a23.x, b01.x); ffma2(acc[2][1], a23.x, b01.y);
            ffma2(acc[2][2], a23.x, b23.x); ffma2(acc[2][3], a23.x, b23.y);
            ffma2(acc[3][0], a23.y, b01.x); ffma2(acc[3][1], a23.y, b01.y);
            ffma2(acc[3][2], a23.y, b23.x); ffma2(acc[3][3], a23.y, b23.y);
        }
        if (kb < 32) {
            int q = p ^ 1;
            *(float2*)&sA[q][akc + 0][arow0 * 2] = make_float2(ra0.x, ra0.x);
            *(float2*)&sA[q][akc + 1][arow0 * 2] = make_float2(ra0.y, ra0.y);
            *(float2*)&sA[q][akc + 2][arow0 * 2] = make_float2(ra0.z, ra0.z);
            *(float2*)&sA[q][akc + 3][arow0 * 2] = make_float2(ra0.w, ra0.w);
            *(float2*)&sA[q][akc + 0][arow1 * 2] = make_float2(ra1.x, ra1.x);
            *(float2*)&sA[q][akc + 1][arow1 * 2] = make_float2(ra1.y, ra1.y);
            *(float2*)&sA[q][akc + 2][arow1 * 2] = make_float2(ra1.z, ra1.z);
            *(float2*)&sA[q][akc + 3][arow1 * 2] = make_float2(ra1.w, ra1.w);
            *(float4*)&sB[q][bk0][bn]     = rb0;
            *(float4*)&sB[q][bk0 + 8][bn] = rb1;
            __syncthreads();
            p = q;
        }
    }

    // epilogue — strict ownership
    int m0;
    bool wvalid;
    float bv[4];
    if (by < 7) {
        m0 = by * 64 + ty * 4;
        wvalid = (m0 < 400);                 // m0 multiple of 4; 400 aligned
#pragma unroll
        for (int i = 0; i < 4; i++) bv[i] = wvalid ? b_cls[m0 + i] : 0.f;
    } else {
        m0 = 400 + ty * 4;
        wvalid = (ty < 8);                   // cols 400..428 (+3) <= 431
#pragma unroll
        for (int i = 0; i < 4; i++) {
            int r = ty * 4 + i;
            bv[i] = (r < 5) ? b_obj[r] : ((r < 25) ? b_reg[r - 5] : 0.f);
        }
    }
    if (wvalid) {
#pragma unroll
        for (int jp = 0; jp < 4; jp++) {
            float2 c0 = unpk(acc[0][jp]), c1 = unpk(acc[1][jp]);
            float2 c2 = unpk(acc[2][jp]), c3 = unpk(acc[3][jp]);
            int n = n0 + tx * 8 + jp * 2;
            *(float4*)&g_outmat[n * MCOLS + m0] =
                make_float4(c0.x + bv[0], c1.x + bv[1], c2.x + bv[2], c3.x + bv[3]);
            *(float4*)&g_outmat[(n + 1) * MCOLS + m0] =
                make_float4(c0.y + bv[0], c1.y + bv[1], c2.y + bv[2], c3.y + bv[3]);
        }
    }
}

// ---------------------------------------------------------------------------
// Decode: 4 threads per box, float4 scans, shfl argmax (first-max semantics).
__global__ __launch_bounds__(256) void box_kernel(float* __restrict__ dout) {
    int t = blockIdx.x * 256 + threadIdx.x;   // 32000 threads
    int i = t >> 2;
    int q = t & 3;
    int cell = i / BPC;
    int a    = i - cell * BPC;
    const float* row = g_outmat + cell * MCOLS;
    const float* cl  = row + a * NCLS + q * 20;

    float best = -1e30f; int bi = 0;
#pragma unroll
    for (int v = 0; v < 5; v++) {
        float4 f = *(const float4*)(cl + v * 4);
        int c0 = q * 20 + v * 4;
        if (f.x > best) { best = f.x; bi = c0; }
        if (f.y > best) { best = f.y; bi = c0 + 1; }
        if (f.z > best) { best = f.z; bi = c0 + 2; }
        if (f.w > best) { best = f.w; bi = c0 + 3; }
    }
#pragma unroll
    for (int off = 1; off < 4; off <<= 1) {
        float ov = __shfl_xor_sync(0xffffffffu, best, off);
        int   oi = __shfl_xor_sync(0xffffffffu, bi, off);
        if (ov > best || (ov == best && oi < bi)) { best = ov; bi = oi; }
    }
    if (q != 0) return;

    float obj   = row[400 + a];
    float score = sqrtf(sigmoidf_(obj) * sigmoidf_(best));

    float txv = row[405 + a * 4 + 0];
    float tyv = row[405 + a * 4 + 1];
    float twv = row[405 + a * 4 + 2];
    float thv = row[405 + a * 4 + 3];

    float ax = (float)(cell % FMP);
    float ay = (float)(cell / FMP);
    float cx = (sigmoidf_(txv) + ax) * 32.f;
    float cy = (sigmoidf_(tyv) + ay) * 32.f;
    float w  = expf(twv) * c_anchor_w[a];
    float h  = expf(thv) * c_anchor_h[a];

    float x1 = cx - 0.5f * w, y1 = cy - 0.5f * h;
    float x2 = cx + 0.5f * w, y2 = cy + 0.5f * h;

    *(float4*)(dout + i * 4) = make_float4(x1, y1, x2, y2);
    dout[OUT_SCORE + i] = score;
    dout[OUT_LABEL + i] = (float)bi;

    *(float4*)(g_b2 + i * 4) = make_float4(x1 - 0.5f * x2, y1 - 0.5f * y2,
                                           x1 + 0.5f * x2, y1 + 0.5f * y2);
    g_score[i] = score;

    int slot = atomicAdd(&g_cls_count[bi], 1);
    g_cls_list[bi * NBOX + slot] = i;
}

// ---------------------------------------------------------------------------
// Per-class NMS. Fast path (n <= 512): rank-sort + IoU bitmatrix + warp greedy.
#define NMS_SMEM 136000
#define NMS_CAP  512

__global__ __launch_bounds__(256) void nms_kernel(float* __restrict__ dout) {
    extern __shared__ char smem[];
    const int c = blockIdx.x;
    const int n = g_cls_count[c];
    const int* list = g_cls_list + c * NBOX;
    const int tid = threadIdx.x;

    if (n <= NMS_CAP) {
        int*      s_lg = (int*)smem;
        float*    s_ls = (float*)(smem + 2048);
        int*      s_si = (int*)(smem + 4096);
        float*    s_ss = (float*)(smem + 6144);
        float*    s_x1 = (float*)(smem + 8192);
        float*    s_y1 = (float*)(smem + 10240);
        float*    s_x2 = (float*)(smem + 12288);
        float*    s_y2 = (float*)(smem + 14336);
        float*    s_ar = (float*)(smem + 16384);
        unsigned* s_vb = (unsigned*)(smem + 18432);
        unsigned* s_sw = (unsigned*)(smem + 18496);
        unsigned* s_M  = (unsigned*)(smem + 18560);
        const int W = (n + 31) >> 5;

        for (int t = tid; t < n; t += 256) { int gi = list[t]; s_lg[t] = gi; s_ls[t] = g_score[gi]; }
        if (tid < 16) s_vb[tid] = 0u;
        __syncthreads();

        for (int t = tid; t < n; t += 256) {
            float st = s_ls[t]; int gt = s_lg[t]; int r = 0;
            for (int j = 0; j < n; j++) {
                float sj = s_ls[j];
                r += (sj > st) || (sj == st && s_lg[j] < gt);
            }
            s_si[r] = gt; s_ss[r] = st;
            float x1 = g_b2[gt * 4 + 0], y1 = g_b2[gt * 4 + 1];
            float x2 = g_b2[gt * 4 + 2], y2 = g_b2[gt * 4 + 3];
            s_x1[r] = x1; s_y1[r] = y1; s_x2[r] = x2; s_y2[r] = y2;
            s_ar[r] = (x2 - x1) * (y2 - y1);
            if (st >= CONF_TH) atomicOr(&s_vb[r >> 5], 1u << (r & 31));
        }
        __syncthreads();

        for (int t = tid; t < n * W; t += 256) {
            int k = t / W, w = t - k * W;
            float kx1 = s_x1[k], ky1 = s_y1[k], kx2 = s_x2[k], ky2 = s_y2[k], ka = s_ar[k];
            unsigned bits = 0;
            int jbase = w * 32;
            int jend = min(jbase + 32, n);
            for (int j = max(jbase, k + 1); j < jend; j++) {
                float xx1 = fmaxf(kx1, s_x1[j]);
                float yy1 = fmaxf(ky1, s_y1[j]);
                float xx2 = fminf(kx2, s_x2[j]);
                float yy2 = fminf(ky2, s_y2[j]);
                float inter = fmaxf(1e-10f, xx2 - xx1) * fmaxf(1e-10f, yy2 - yy1);
                float iou = inter / (ka + s_ar[j] - inter + 1e-14f);
                if (iou > NMS_TH) bits |= 1u << (j & 31);
            }
            s_M[k * W + w] = bits;
        }
        __syncthreads();

        if (tid < 32) {
            unsigned live = (tid < W) ? s_vb[tid] : 0u;
            for (int k = 0; k < n; k++) {
                unsigned lw = __shfl_sync(0xffffffffu, live, k >> 5);
                if (lw & (1u << (k & 31))) {
                    if (tid < W) live &= ~s_M[k * W + tid];
                }
            }
            if (tid < 16) s_sw[tid] = (tid < W) ? live : 0u;
        }
        __syncthreads();

        for (int t = tid; t < n; t += 256) {
            float kv = ((s_sw[t >> 5] >> (t & 31)) & 1u) ? 1.f : 0.f;
            dout[OUT_KEEP + s_si[t]] = kv;
        }
    } else {
        float* s_ls = (float*)smem;
        int*   s_lg = (int*)(smem + 32000);
        int*   s_si = (int*)(smem + 64000);
        float* s_ss = (float*)(smem + 96000);
        unsigned char* s_supp = (unsigned char*)(smem + 128000);

        for (int t = tid; t < n; t += 256) {
            int gi = list[t];
            s_lg[t] = gi; s_ls[t] = g_score[gi];
        }
        __syncthreads();
        for (int t = tid; t < n; t += 256) {
            float st = s_ls[t]; int gt = s_lg[t]; int r = 0;
            for (int j = 0; j < n; j++) {
                float sj = s_ls[j];
                r += (sj > st) || (sj == st && s_lg[j] < gt);
            }
            s_si[r] = gt; s_ss[r] = st;
        }
        for (int t = tid; t < n; t += 256) s_supp[t] = 0;
        __syncthreads();

        for (int k = 0; k < n; k++) {
            if (!s_supp[k] && s_ss[k] >= CONF_TH) {
                int gk = s_si[k];
                float bx1 = g_b2[gk * 4 + 0], by1 = g_b2[gk * 4 + 1];
                float bx2 = g_b2[gk * 4 + 2], by2 = g_b2[gk * 4 + 3];
                float ak = (bx2 - bx1) * (by2 - by1);
                for (int j = k + 1 + tid; j < n; j += 256) {
                    if (s_supp[j]) continue;
                    int gj = s_si[j];
                    float cx1 = g_b2[gj * 4 + 0], cy1 = g_b2[gj * 4 + 1];
                    float cx2 = g_b2[gj * 4 + 2], cy2 = g_b2[gj * 4 + 3];
                    float xx1 = fmaxf(bx1, cx1);
                    float yy1 = fmaxf(by1, cy1);
                    float xx2 = fminf(bx2, cx2);
                    float yy2 = fminf(by2, cy2);
                    float inter = fmaxf(1e-10f, xx2 - xx1) * fmaxf(1e-10f, yy2 - yy1);
                    float aj = (cx2 - cx1) * (cy2 - cy1);
                    float iou = inter / (ak + aj - inter + 1e-14f);
                    if (iou > NMS_TH) s_supp[j] = 1;
                }
            }
            __syncthreads();
        }
        for (int t = tid; t < n; t += 256) {
            float kv = (s_ss[t] >= CONF_TH && !s_supp[t]) ? 1.f : 0.f;
            dout[OUT_KEEP + s_si[t]] = kv;
        }
    }
}

// ---------------------------------------------------------------------------
extern "C" void kernel_launch(void* const* d_in, const int* in_sizes, int n_in,
                              void* d_out, int out_size) {
    const float* cls_feat = (const float*)d_in[0];
    const float* reg_feat = (const float*)d_in[1];
    const float* w_obj    = (const float*)d_in[2];
    const float* b_obj    = (const float*)d_in[3];
    const float* w_cls    = (const float*)d_in[4];
    const float* b_cls    = (const float*)d_in[5];
    const float* w_reg    = (const float*)d_in[6];
    const float* b_reg    = (const float*)d_in[7];
    float* out = (float*)d_out;

    cudaFuncSetAttribute(nms_kernel, cudaFuncAttributeMaxDynamicSharedMemorySize, NMS_SMEM);

    gemm_kernel<<<dim3(25, 8), 128>>>(cls_feat, reg_feat, w_obj, b_obj,
                                      w_cls, b_cls, w_reg, b_reg);
    box_kernel<<<125, 256>>>(out);
    nms_kernel<<<NCLS, 256, NMS_SMEM>>>(out);
}

// round 9
// speedup vs baseline: 1.3991x; 1.3991x over previous
#include <cuda_runtime.h>
#include <math.h>
#include <stdint.h>

// ---------------------------------------------------------------------------
#define FMP     40
#define HW      1600
#define BPC     5
#define NBOX    8000
#define NCLS    80
#define KDIM    512
#define MCOLS   432
#define CONF_TH 0.3f
#define NMS_TH  0.5f

#define OUT_SCORE  32000
#define OUT_LABEL  40000
#define OUT_KEEP   48000

__constant__ float c_anchor_w[5] = {17.f, 55.f, 92.f, 202.f, 289.f};
__constant__ float c_anchor_h[5] = {25.f, 75.f, 206.f, 21.f, 311.f};

__device__ float g_outmat[HW * MCOLS];   // [cell][col]: 0..399 cls, 400..404 obj, 405..424 reg, pad
__device__ float g_b2[NBOX * 4];
__device__ float g_score[NBOX];
__device__ int   g_cls_count[NCLS];
__device__ int   g_cls_list[NCLS * NBOX];

typedef unsigned long long ull;
typedef unsigned int uint32;

__device__ __forceinline__ ull dup2(float a) {
    ull r; asm("mov.b64 %0, {%1, %1};" : "=l"(r) : "f"(a)); return r;
}
__device__ __forceinline__ void ffma2(ull& d, ull a, ull b) {
    asm("fma.rn.f32x2 %0, %1, %2, %0;" : "+l"(d) : "l"(a), "l"(b));
}
__device__ __forceinline__ float2 unpk(ull v) {
    float2 f; asm("mov.b64 {%0, %1}, %2;" : "=f"(f.x), "=f"(f.y) : "l"(v)); return f;
}
__device__ __forceinline__ float sigmoidf_(float x) { return 1.f / (1.f + expf(-x)); }

__device__ __forceinline__ void cp_async16(uint32 smem_dst, const void* gsrc) {
    asm volatile("cp.async.cg.shared.global [%0], [%1], 16;"
                 :: "r"(smem_dst), "l"(gsrc) : "memory");
}
__device__ __forceinline__ void cp_commit() {
    asm volatile("cp.async.commit_group;" ::: "memory");
}
__device__ __forceinline__ void cp_wait2() {
    asm volatile("cp.async.wait_group 2;" ::: "memory");
}

// ---------------------------------------------------------------------------
// GEMM (f32x2, M packed into lanes): tile M32 x N64, BK=16, 128 threads,
// thread tile 8m x 2n. Acc pairs hold (m, m+1) -> A read as natural pairs
// (2x LDS.128, warp-broadcast), only B duplicated (1 LDS.64 + 2 MOV).
// B: 4-stage cp.async pipeline (issued 3 k-blocks ahead). A: reg-staged
// double buffer. Grid (25 n-tiles, 14 m-tiles) = 350 blocks.
// Ownership: m-tiles 0..12 write only cols<400; tile 13 owns 400..431.
#define NKB (KDIM / 16)   // 32 k-blocks
__global__ __launch_bounds__(128) void gemm_kernel(
    const float* __restrict__ cls_feat, const float* __restrict__ reg_feat,
    const float* __restrict__ w_obj, const float* __restrict__ b_obj,
    const float* __restrict__ w_cls, const float* __restrict__ b_cls,
    const float* __restrict__ w_reg, const float* __restrict__ b_reg)
{
    __shared__ __align__(16) float sA[2][16][32];   // [buf][k][m]
    __shared__ __align__(16) float sB[4][16][64];   // [stage][k][n]

    const int bx = blockIdx.x;           // n-tile 0..24
    const int by = blockIdx.y;           // m-tile 0..13
    const int tid = threadIdx.x;         // 0..127
    const int tx = tid & 31;             // n-group: 2n each (warp-uniform ty!)
    const int ty = tid >> 5;             // m-group: 8m each (== warp id)
    const int n0 = bx * 64;
    const int mbase = by * 32;

    if (bx == 0 && by == 0 && tid < NCLS) g_cls_count[tid] = 0;

    const float* F = (by < 13) ? cls_feat : reg_feat;

    // ---- A-load job: one float4 per thread per k-block ----
    const int am  = tid & 31;            // m within tile
    const int akc = (tid >> 5) * 4;      // k offset 0/4/8/12
    const float* ap = 0;
    if (by < 13) { int gm = mbase + am; if (gm < 400) ap = w_cls + gm * KDIM; }
    else {
        if (am < 5)       ap = w_obj + am * KDIM;
        else if (am < 25) ap = w_reg + (am - 5) * KDIM;
    }

    // ---- B cp.async job: 2x 16B per thread per k-block ----
    const int bkk0 = tid >> 4;           // k row 0..7
    const int bnn0 = (tid & 15) * 4;
    const int bkk1 = bkk0 + 8;           // k row 8..15
    uint32 sb_base = (uint32)__cvta_generic_to_shared(&sB[0][0][0]);

    auto issue_B = [&](int kb) {
        const int s = kb & 3;
        const float* g0 = F + (kb * 16 + bkk0) * HW + n0 + bnn0;
        const float* g1 = F + (kb * 16 + bkk1) * HW + n0 + bnn0;
        uint32 d0 = sb_base + (uint32)(((s * 16 + bkk0) * 64 + bnn0) * 4);
        uint32 d1 = sb_base + (uint32)(((s * 16 + bkk1) * 64 + bnn0) * 4);
        cp_async16(d0, g0);
        cp_async16(d1, g1);
    };
    auto load_A = [&](int kb) -> float4 {
        return ap ? *(const float4*)(ap + kb * 16 + akc)
                  : make_float4(0.f, 0.f, 0.f, 0.f);
    };
    auto store_A = [&](float4 v, int buf) {
        sA[buf][akc + 0][am] = v.x;
        sA[buf][akc + 1][am] = v.y;
        sA[buf][akc + 2][am] = v.z;
        sA[buf][akc + 3][am] = v.w;
    };

    ull c[2][4];
#pragma unroll
    for (int j = 0; j < 2; j++)
#pragma unroll
        for (int i = 0; i < 4; i++) c[j][i] = 0ULL;

    // prologue: B stages 0..2 in flight, A block 0 in smem
    issue_B(0); cp_commit();
    issue_B(1); cp_commit();
    issue_B(2); cp_commit();
    store_A(load_A(0), 0);

    for (int kb = 0; kb < NKB; kb++) {
        cp_wait2();              // B(kb) complete (<=2 newer groups pending)
        __syncthreads();         // visibility of sB stage + sA buffer

        if (kb + 3 < NKB) issue_B(kb + 3);
        cp_commit();             // empty group when not issuing (keeps count)

        float4 ran;
        if (kb + 1 < NKB) ran = load_A(kb + 1);

        const int p = kb & 1;
        const int s = kb & 3;
#pragma unroll
        for (int k = 0; k < 16; k++) {
            ulonglong2 a01 = *(const ulonglong2*)&sA[p][k][ty * 8];
            ulonglong2 a23 = *(const ulonglong2*)&sA[p][k][ty * 8 + 4];
            float2 bb = *(const float2*)&sB[s][k][tx * 2];
            ull b0 = dup2(bb.x);
            ull b1 = dup2(bb.y);
            ffma2(c[0][0], a01.x, b0); ffma2(c[0][1], a01.y, b0);
            ffma2(c[0][2], a23.x, b0); ffma2(c[0][3], a23.y, b0);
            ffma2(c[1][0], a01.x, b1); ffma2(c[1][1], a01.y, b1);
            ffma2(c[1][2], a23.x, b1); ffma2(c[1][3], a23.y, b1);
        }
        if (kb + 1 < NKB) store_A(ran, (kb + 1) & 1);
    }

    // ---- epilogue: strict column ownership ----
    int m0;
    bool wvalid;
    float bv[8];
    if (by < 13) {
        m0 = mbase + ty * 8;
        wvalid = (m0 < 400);     // 400 lands exactly on a ty-group boundary
#pragma unroll
        for (int i = 0; i < 8; i++) bv[i] = wvalid ? b_cls[m0 + i] : 0.f;
    } else {
        m0 = 400 + ty * 8;       // cols 400..431 (425..431 pad)
        wvalid = true;
#pragma unroll
        for (int i = 0; i < 8; i++) {
            int r = ty * 8 + i;
            bv[i] = (r < 5) ? b_obj[r] : ((r < 25) ? b_reg[r - 5] : 0.f);
        }
    }
    if (wvalid) {
#pragma unroll
        for (int j = 0; j < 2; j++) {
            int n = n0 + tx * 2 + j;
            float2 p0 = unpk(c[j][0]), p1 = unpk(c[j][1]);
            float2 p2 = unpk(c[j][2]), p3 = unpk(c[j][3]);
            float* dst = &g_outmat[n * MCOLS + m0];
            *(float4*)dst =
                make_float4(p0.x + bv[0], p0.y + bv[1], p1.x + bv[2], p1.y + bv[3]);
            *(float4*)(dst + 4) =
                make_float4(p2.x + bv[4], p2.y + bv[5], p3.x + bv[6], p3.y + bv[7]);
        }
    }
}

// ---------------------------------------------------------------------------
// Decode: 4 threads per box, float4 scans, shfl argmax (first-max semantics).
__global__ __launch_bounds__(256) void box_kernel(float* __restrict__ dout) {
    int t = blockIdx.x * 256 + threadIdx.x;   // 32000 threads
    int i = t >> 2;
    int q = t & 3;
    int cell = i / BPC;
    int a    = i - cell * BPC;
    const float* row = g_outmat + cell * MCOLS;
    const float* cl  = row + a * NCLS + q * 20;

    float best = -1e30f; int bi = 0;
#pragma unroll
    for (int v = 0; v < 5; v++) {
        float4 f = *(const float4*)(cl + v * 4);
        int c0 = q * 20 + v * 4;
        if (f.x > best) { best = f.x; bi = c0; }
        if (f.y > best) { best = f.y; bi = c0 + 1; }
        if (f.z > best) { best = f.z; bi = c0 + 2; }
        if (f.w > best) { best = f.w; bi = c0 + 3; }
    }
#pragma unroll
    for (int off = 1; off < 4; off <<= 1) {
        float ov = __shfl_xor_sync(0xffffffffu, best, off);
        int   oi = __shfl_xor_sync(0xffffffffu, bi, off);
        if (ov > best || (ov == best && oi < bi)) { best = ov; bi = oi; }
    }
    if (q != 0) return;

    float obj   = row[400 + a];
    float score = sqrtf(sigmoidf_(obj) * sigmoidf_(best));

    float txv = row[405 + a * 4 + 0];
    float tyv = row[405 + a * 4 + 1];
    float twv = row[405 + a * 4 + 2];
    float thv = row[405 + a * 4 + 3];

    float ax = (float)(cell % FMP);
    float ay = (float)(cell / FMP);
    float cx = (sigmoidf_(txv) + ax) * 32.f;
    float cy = (sigmoidf_(tyv) + ay) * 32.f;
    float w  = expf(twv) * c_anchor_w[a];
    float h  = expf(thv) * c_anchor_h[a];

    float x1 = cx - 0.5f * w, y1 = cy - 0.5f * h;
    float x2 = cx + 0.5f * w, y2 = cy + 0.5f * h;

    *(float4*)(dout + i * 4) = make_float4(x1, y1, x2, y2);
    dout[OUT_SCORE + i] = score;
    dout[OUT_LABEL + i] = (float)bi;

    *(float4*)(g_b2 + i * 4) = make_float4(x1 - 0.5f * x2, y1 - 0.5f * y2,
                                           x1 + 0.5f * x2, y1 + 0.5f * y2);
    g_score[i] = score;

    int slot = atomicAdd(&g_cls_count[bi], 1);
    g_cls_list[bi * NBOX + slot] = i;
}

// ---------------------------------------------------------------------------
// Per-class NMS. Fast path (n <= 512): rank-sort + IoU bitmatrix + warp greedy.
#define NMS_SMEM 136000
#define NMS_CAP  512

__global__ __launch_bounds__(256) void nms_kernel(float* __restrict__ dout) {
    extern __shared__ char smem[];
    const int c = blockIdx.x;
    const int n = g_cls_count[c];
    const int* list = g_cls_list + c * NBOX;
    const int tid = threadIdx.x;

    if (n <= NMS_CAP) {
        int*      s_lg = (int*)smem;
        float*    s_ls = (float*)(smem + 2048);
        int*      s_si = (int*)(smem + 4096);
        float*    s_ss = (float*)(smem + 6144);
        float*    s_x1 = (float*)(smem + 8192);
        float*    s_y1 = (float*)(smem + 10240);
        float*    s_x2 = (float*)(smem + 12288);
        float*    s_y2 = (float*)(smem + 14336);
        float*    s_ar = (float*)(smem + 16384);
        unsigned* s_vb = (unsigned*)(smem + 18432);
        unsigned* s_sw = (unsigned*)(smem + 18496);
        unsigned* s_M  = (unsigned*)(smem + 18560);
        const int W = (n + 31) >> 5;

        for (int t = tid; t < n; t += 256) { int gi = list[t]; s_lg[t] = gi; s_ls[t] = g_score[gi]; }
        if (tid < 16) s_vb[tid] = 0u;
        __syncthreads();

        for (int t = tid; t < n; t += 256) {
            float st = s_ls[t]; int gt = s_lg[t]; int r = 0;
            for (int j = 0; j < n; j++) {
                float sj = s_ls[j];
                r += (sj > st) || (sj == st && s_lg[j] < gt);
            }
            s_si[r] = gt; s_ss[r] = st;
            float x1 = g_b2[gt * 4 + 0], y1 = g_b2[gt * 4 + 1];
            float x2 = g_b2[gt * 4 + 2], y2 = g_b2[gt * 4 + 3];
            s_x1[r] = x1; s_y1[r] = y1; s_x2[r] = x2; s_y2[r] = y2;
            s_ar[r] = (x2 - x1) * (y2 - y1);
            if (st >= CONF_TH) atomicOr(&s_vb[r >> 5], 1u << (r & 31));
        }
        __syncthreads();

        for (int t = tid; t < n * W; t += 256) {
            int k = t / W, w = t - k * W;
            float kx1 = s_x1[k], ky1 = s_y1[k], kx2 = s_x2[k], ky2 = s_y2[k], ka = s_ar[k];
            unsigned bits = 0;
            int jbase = w * 32;
            int jend = min(jbase + 32, n);
            for (int j = max(jbase, k + 1); j < jend; j++) {
                float xx1 = fmaxf(kx1, s_x1[j]);
                float yy1 = fmaxf(ky1, s_y1[j]);
                float xx2 = fminf(kx2, s_x2[j]);
                float yy2 = fminf(ky2, s_y2[j]);
                float inter = fmaxf(1e-10f, xx2 - xx1) * fmaxf(1e-10f, yy2 - yy1);
                float iou = inter / (ka + s_ar[j] - inter + 1e-14f);
                if (iou > NMS_TH) bits |= 1u << (j & 31);
            }
            s_M[k * W + w] = bits;
        }
        __syncthreads();

        if (tid < 32) {
            unsigned live = (tid < W) ? s_vb[tid] : 0u;
            for (int k = 0; k < n; k++) {
                unsigned lw = __shfl_sync(0xffffffffu, live, k >> 5);
                if (lw & (1u << (k & 31))) {
                    if (tid < W) live &= ~s_M[k * W + tid];
                }
            }
            if (tid < 16) s_sw[tid] = (tid < W) ? live : 0u;
        }
        __syncthreads();

        for (int t = tid; t < n; t += 256) {
            float kv = ((s_sw[t >> 5] >> (t & 31)) & 1u) ? 1.f : 0.f;
            dout[OUT_KEEP + s_si[t]] = kv;
        }
    } else {
        float* s_ls = (float*)smem;
        int*   s_lg = (int*)(smem + 32000);
        int*   s_si = (int*)(smem + 64000);
        float* s_ss = (float*)(smem + 96000);
        unsigned char* s_supp = (unsigned char*)(smem + 128000);

        for (int t = tid; t < n; t += 256) {
            int gi = list[t];
            s_lg[t] = gi; s_ls[t] = g_score[gi];
        }
        __syncthreads();
        for (int t = tid; t < n; t += 256) {
            float st = s_ls[t]; int gt = s_lg[t]; int r = 0;
            for (int j = 0; j < n; j++) {
                float sj = s_ls[j];
                r += (sj > st) || (sj == st && s_lg[j] < gt);
            }
            s_si[r] = gt; s_ss[r] = st;
        }
        for (int t = tid; t < n; t += 256) s_supp[t] = 0;
        __syncthreads();

        for (int k = 0; k < n; k++) {
            if (!s_supp[k] && s_ss[k] >= CONF_TH) {
                int gk = s_si[k];
                float bx1 = g_b2[gk * 4 + 0], by1 = g_b2[gk * 4 + 1];
                float bx2 = g_b2[gk * 4 + 2], by2 = g_b2[gk * 4 + 3];
                float ak = (bx2 - bx1) * (by2 - by1);
                for (int j = k + 1 + tid; j < n; j += 256) {
                    if (s_supp[j]) continue;
                    int gj = s_si[j];
                    float cx1 = g_b2[gj * 4 + 0], cy1 = g_b2[gj * 4 + 1];
                    float cx2 = g_b2[gj * 4 + 2], cy2 = g_b2[gj * 4 + 3];
                    float xx1 = fmaxf(bx1, cx1);
                    float yy1 = fmaxf(by1, cy1);
                    float xx2 = fminf(bx2, cx2);
                    float yy2 = fminf(by2, cy2);
                    float inter = fmaxf(1e-10f, xx2 - xx1) * fmaxf(1e-10f, yy2 - yy1);
                    float aj = (cx2 - cx1) * (cy2 - cy1);
                    float iou = inter / (ak + aj - inter + 1e-14f);
                    if (iou > NMS_TH) s_supp[j] = 1;
                }
            }
            __syncthreads();
        }
        for (int t = tid; t < n; t += 256) {
            float kv = (s_ss[t] >= CONF_TH && !s_supp[t]) ? 1.f : 0.f;
            dout[OUT_KEEP + s_si[t]] = kv;
        }
    }
}

// ---------------------------------------------------------------------------
extern "C" void kernel_launch(void* const* d_in, const int* in_sizes, int n_in,
                              void* d_out, int out_size) {
    const float* cls_feat = (const float*)d_in[0];
    const float* reg_feat = (const float*)d_in[1];
    const float* w_obj    = (const float*)d_in[2];
    const float* b_obj    = (const float*)d_in[3];
    const float* w_cls    = (const float*)d_in[4];
    const float* b_cls    = (const float*)d_in[5];
    const float* w_reg    = (const float*)d_in[6];
    const float* b_reg    = (const float*)d_in[7];
    float* out = (float*)d_out;

    cudaFuncSetAttribute(nms_kernel, cudaFuncAttributeMaxDynamicSharedMemorySize, NMS_SMEM);

    gemm_kernel<<<dim3(25, 14), 128>>>(cls_feat, reg_feat, w_obj, b_obj,
                                       w_cls, b_cls, w_reg, b_reg);
    box_kernel<<<125, 256>>>(out);
    nms_kernel<<<NCLS, 256, NMS_SMEM>>>(out);
}